// round 13
// baseline (speedup 1.0000x reference)
#include <cuda_runtime.h>
#include <cuda_bf16.h>
#include <cstdint>
#include <cstddef>

static constexpr int   N     = 4096;
static constexpr int   NB    = 32;            // 128-tiles per side
static constexpr int   NT    = 128;           // 32-tiles per side
static constexpr int   TOT_ITERS = 12;        // 10 bf16 + 2 fp32 polish (even -> m ends in g_m[0])
static constexpr int   SPLIT = 10;
static constexpr float CINV  = 1.0f / 1.000001f;

// ---------------------------------------------------------------------------
// Device scratch (allocation-free rule: __device__ globals)
// ---------------------------------------------------------------------------
static __device__ float         g_Js[(size_t)N * N];  // 64 MB symmetrized J (fp32)
static __device__ __nv_bfloat16 g_G [(size_t)N * N];  // 32 MB: Js(bf16) during iters, then G
static __device__ __nv_bfloat16 g_H [(size_t)N * N];  // 32 MB: H = G + G^2
static __device__ float         g_m [2][N];
static __device__ float         g_d [N];
static __device__ float         g_w [N];

// ---------------------------------------------------------------------------
// PTX wrappers (baseline PTX only: sm_75/80/90 non-'a' features)
// ---------------------------------------------------------------------------
__device__ __forceinline__ void mma_bf16(float* c, const uint32_t* a, const uint32_t* b) {
    asm volatile(
        "mma.sync.aligned.m16n8k16.row.col.f32.bf16.bf16.f32 "
        "{%0,%1,%2,%3}, {%4,%5,%6,%7}, {%8,%9}, {%0,%1,%2,%3};\n"
        : "+f"(c[0]), "+f"(c[1]), "+f"(c[2]), "+f"(c[3])
        : "r"(a[0]), "r"(a[1]), "r"(a[2]), "r"(a[3]), "r"(b[0]), "r"(b[1]));
}
__device__ __forceinline__ void ldmatrix_x4(uint32_t* r, uint32_t addr) {
    asm volatile("ldmatrix.sync.aligned.m8n8.x4.shared.b16 {%0,%1,%2,%3}, [%4];"
                 : "=r"(r[0]), "=r"(r[1]), "=r"(r[2]), "=r"(r[3]) : "r"(addr));
}
__device__ __forceinline__ uint32_t smem_u32(const void* p) {
    uint32_t a;
    asm("{ .reg .u64 t; cvta.to.shared.u64 t, %1; cvt.u32.u64 %0, t; }" : "=r"(a) : "l"(p));
    return a;
}
__device__ __forceinline__ void cp16(uint32_t dst, const void* src) {
    asm volatile("cp.async.cg.shared.global [%0], [%1], 16;" :: "r"(dst), "l"(src));
}
#define CP_COMMIT()  asm volatile("cp.async.commit_group;" ::: "memory")
#define CP_WAITN(n)  asm volatile("cp.async.wait_group %0;" :: "n"(n) : "memory")

// 1D bulk async copy (TMA/UBLKCP) + mbarrier — sm_90 baseline PTX
__device__ __forceinline__ void cp_bulk(uint32_t dst, const void* src, uint32_t bytes,
                                        uint32_t mbar) {
    asm volatile(
        "cp.async.bulk.shared::cta.global.mbarrier::complete_tx::bytes [%0], [%1], %2, [%3];"
        :: "r"(dst), "l"(src), "r"(bytes), "r"(mbar) : "memory");
}
#define MBAR_INIT(addr, cnt) \
    asm volatile("mbarrier.init.shared.b64 [%0], %1;" :: "r"(addr), "r"(cnt) : "memory")
#define MBAR_EXPECT_TX(addr, bytes) \
    asm volatile("mbarrier.arrive.expect_tx.shared.b64 _, [%0], %1;" \
                 :: "r"(addr), "r"(bytes) : "memory")
__device__ __forceinline__ void mbar_wait(uint32_t mbar, uint32_t parity) {
    uint32_t done;
    asm volatile(
        "{\n\t.reg .pred p;\n\t"
        "mbarrier.try_wait.parity.shared.b64 p, [%1], %2;\n\t"
        "selp.b32 %0, 1, 0, p;\n\t}"
        : "=r"(done) : "r"(mbar), "r"(parity) : "memory");
    while (!done) {
        asm volatile(
            "{\n\t.reg .pred p;\n\t"
            "mbarrier.try_wait.parity.shared.b64 p, [%1], %2;\n\t"
            "selp.b32 %0, 1, 0, p;\n\t}"
            : "=r"(done) : "r"(mbar), "r"(parity) : "memory");
    }
}

// ---------------------------------------------------------------------------
// k_zero_tri: zero cov lower triangle + diagonal
// ---------------------------------------------------------------------------
__global__ void k_zero_tri(float* out, long long covBase) {
    int r = blockIdx.x;
    float* row = out + covBase + (size_t)r * N;
    int nz = r + 1;
    int nq = nz >> 2;
    float4* row4 = (float4*)row;
    for (int q = threadIdx.x; q < nq; q += blockDim.x)
        row4[q] = make_float4(0.f, 0.f, 0.f, 0.f);
    int tail = nq << 2;
    if (threadIdx.x < nz - tail) row[tail + threadIdx.x] = 0.f;
}

// ---------------------------------------------------------------------------
// k_prep: Js = sym(J) with zero diag (fp32) + bf16 copy; tile-pair version
// ---------------------------------------------------------------------------
__global__ void k_prep(const float* __restrict__ J) {
    int rem = blockIdx.x;
    int bi = 0;
    while (rem >= NT - bi) { rem -= NT - bi; bi++; }
    int bj = bi + rem;
    __shared__ float ta[32][33];
    __shared__ float tb[32][33];
    int r = threadIdx.y, c = threadIdx.x;
    ta[r][c] = J[(size_t)(bi * 32 + r) * N + (bj * 32 + c)];
    tb[r][c] = J[(size_t)(bj * 32 + r) * N + (bi * 32 + c)];
    __syncthreads();
    {
        int gi = bi * 32 + r, gj = bj * 32 + c;
        float v = (gi == gj) ? 0.0f : 0.5f * (ta[r][c] + tb[c][r]);
        size_t idx = (size_t)gi * N + gj;
        g_Js[idx] = v;
        g_G[idx]  = __float2bfloat16(v);
    }
    if (bi != bj) {
        int gi = bj * 32 + r, gj = bi * 32 + c;
        float v = 0.5f * (tb[r][c] + ta[c][r]);
        size_t idx = (size_t)gi * N + gj;
        g_Js[idx] = v;
        g_G[idx]  = __float2bfloat16(v);
    }
}

// ---------------------------------------------------------------------------
// m0 = tanh(h)
// ---------------------------------------------------------------------------
__global__ void k_minit(const float* __restrict__ h) {
    int i = blockIdx.x * blockDim.x + threadIdx.x;
    if (i < N) g_m[0][i] = tanhf(h[i]);
}

// ---------------------------------------------------------------------------
// bf16 iteration via cp.async.bulk: 4 rows/CTA, one 8KB bulk copy per row.
// threads 0-127 compute rows 0,1 ; threads 128-255 compute rows 2,3.
// ---------------------------------------------------------------------------
__global__ void __launch_bounds__(256) k_iter_bf16(const float* __restrict__ h, int pin) {
    __shared__ __align__(128) __nv_bfloat16 sj[4][N];   // 32 KB
    __shared__ __align__(8) unsigned long long mbar[4];
    int row0 = blockIdx.x * 4;
    const float* mi_v = g_m[pin];
    const float4* mv = (const float4*)mi_v;
    int tid = threadIdx.x;
    int half = tid >> 7;
    int tcol = tid & 127;
    int r0 = half * 2;
    uint32_t mb0 = smem_u32(&mbar[0]);

    if (tid < 4) MBAR_INIT(mb0 + tid * 8, 1);
    __syncthreads();
    if (tid == 0) {
#pragma unroll
        for (int r = 0; r < 4; r++) {
            MBAR_EXPECT_TX(mb0 + r * 8, N * 2);
            cp_bulk(smem_u32(&sj[r][0]), g_G + (size_t)(row0 + r) * N, N * 2, mb0 + r * 8);
        }
    }

    float s1[2] = {0.f, 0.f}, s2[2] = {0.f, 0.f};
#pragma unroll
    for (int p = 0; p < 2; p++) {
        int r = r0 + p;
        mbar_wait(mb0 + r * 8, 0);
        // row r: 512 uint4 chunks; 128 threads of this half take 4 each
#pragma unroll
        for (int k = 0; k < 4; k++) {
            int cc = tcol + 128 * k;
            float4 ma = mv[2 * cc], mb2 = mv[2 * cc + 1];
            float pa[8] = {ma.x, ma.y, ma.z, ma.w, mb2.x, mb2.y, mb2.z, mb2.w};
            uint4 v = *(const uint4*)&sj[r][cc * 8];
            const __nv_bfloat162* b2 = reinterpret_cast<const __nv_bfloat162*>(&v);
            float2 a0 = __bfloat1622float2(b2[0]);
            float2 a1 = __bfloat1622float2(b2[1]);
            float2 a2 = __bfloat1622float2(b2[2]);
            float2 a3 = __bfloat1622float2(b2[3]);
            float av[8] = {a0.x, a0.y, a1.x, a1.y, a2.x, a2.y, a3.x, a3.y};
#pragma unroll
            for (int e = 0; e < 8; e++) {
                float pb = pa[e] * (1.f - pa[e]);
                s1[p] = fmaf(av[e], pa[e], s1[p]);
                s2[p] = fmaf(av[e] * av[e], pb, s2[p]);
            }
        }
    }

    // reduce: warps 0-3 hold rows 0,1 ; warps 4-7 hold rows 2,3
    __shared__ float rs1[8][2], rs2[8][2];
    int lane = tid & 31, w = tid >> 5;
#pragma unroll
    for (int p = 0; p < 2; p++) {
#pragma unroll
        for (int o = 16; o; o >>= 1) {
            s1[p] += __shfl_xor_sync(0xFFFFFFFFu, s1[p], o);
            s2[p] += __shfl_xor_sync(0xFFFFFFFFu, s2[p], o);
        }
        if (lane == 0) { rs1[w][p] = s1[p]; rs2[w][p] = s2[p]; }
    }
    __syncthreads();
    if (tid < 4) {
        int r = tid;
        int wbase = (r >> 1) * 4;
        int idx = r & 1;
        float a = 0.f, b = 0.f;
#pragma unroll
        for (int ww = 0; ww < 4; ww++) { a += rs1[wbase + ww][idx]; b += rs2[wbase + ww][idx]; }
        int row = row0 + r;
        float mi = mi_v[row];
        g_m[pin ^ 1][row] = 0.5f * (mi + tanhf(h[row] + a - mi * b));
    }
}

// ---------------------------------------------------------------------------
// fp32 polish via cp.async.bulk: 2 rows/CTA, one 16KB bulk copy per row.
// warps 0-3 -> row 0, warps 4-7 -> row 1.
// ---------------------------------------------------------------------------
__global__ void __launch_bounds__(256) k_iter_f32(const float* __restrict__ h, int pin) {
    __shared__ __align__(128) float sj[2][N];           // 32 KB
    __shared__ __align__(8) unsigned long long mbar[2];
    int row0 = blockIdx.x * 2;
    const float* mi_v = g_m[pin];
    const float4* mv = (const float4*)mi_v;
    int tid = threadIdx.x;
    int half = tid >> 7;
    int tcol = tid & 127;
    uint32_t mb0 = smem_u32(&mbar[0]);

    if (tid < 2) MBAR_INIT(mb0 + tid * 8, 1);
    __syncthreads();
    if (tid == 0) {
#pragma unroll
        for (int r = 0; r < 2; r++) {
            MBAR_EXPECT_TX(mb0 + r * 8, N * 4);
            cp_bulk(smem_u32(&sj[r][0]), g_Js + (size_t)(row0 + r) * N, N * 4, mb0 + r * 8);
        }
    }

    mbar_wait(mb0 + half * 8, 0);
    float s1 = 0.f, s2 = 0.f;
    // row `half`: 1024 float4 chunks; 128 threads take 8 each
#pragma unroll
    for (int k = 0; k < 8; k++) {
        int cc = tcol + 128 * k;
        float4 a = *(const float4*)&sj[half][cc * 4];
        float4 mq = mv[cc];
        float pa[4] = {mq.x, mq.y, mq.z, mq.w};
        float av[4] = {a.x, a.y, a.z, a.w};
#pragma unroll
        for (int e = 0; e < 4; e++) {
            float pb = pa[e] * (1.f - pa[e]);
            s1 = fmaf(av[e], pa[e], s1);
            s2 = fmaf(av[e] * av[e], pb, s2);
        }
    }

    __shared__ float rs1[8], rs2[8];
    int lane = tid & 31, w = tid >> 5;
#pragma unroll
    for (int o = 16; o; o >>= 1) {
        s1 += __shfl_xor_sync(0xFFFFFFFFu, s1, o);
        s2 += __shfl_xor_sync(0xFFFFFFFFu, s2, o);
    }
    if (lane == 0) { rs1[w] = s1; rs2[w] = s2; }
    __syncthreads();
    if (tid < 2) {
        int r = tid;
        float a = 0.f, b = 0.f;
#pragma unroll
        for (int ww = 0; ww < 4; ww++) { a += rs1[r * 4 + ww]; b += rs2[r * 4 + ww]; }
        int row = row0 + r;
        float mi = mi_v[row];
        g_m[pin ^ 1][row] = 0.5f * (mi + tanhf(h[row] + a - mi * b));
    }
}

// ---------------------------------------------------------------------------
// k_vec: finalize m, compute d, w, write m to out
// ---------------------------------------------------------------------------
__global__ void k_vec(float* out, int writeM) {
    int i = blockIdx.x * blockDim.x + threadIdx.x;
    if (i < N) {
        float m = g_m[0][i];
        float d = 1.0f - m * m;
        g_d[i] = d;
        g_w[i] = sqrtf(d);
        if (writeM) out[i] = m;
    }
}

// ---------------------------------------------------------------------------
// k_buildG: G_ij = CINV * w_i * G_ij * w_j (in-place over bf16(Js))
// ---------------------------------------------------------------------------
__global__ void k_buildG() {
    size_t q = (size_t)blockIdx.x * blockDim.x + threadIdx.x;
    size_t nq = (size_t)N * N / 8;
    if (q >= nq) return;
    size_t base = q * 8;
    int i = (int)(base >> 12);
    int j = (int)(base & (N - 1));
    uint4 v = *(const uint4*)(g_G + base);
    const __nv_bfloat162* b2 = reinterpret_cast<const __nv_bfloat162*>(&v);
    float s = CINV * g_w[i];
    uint4 outv;
    __nv_bfloat162* o2 = reinterpret_cast<__nv_bfloat162*>(&outv);
#pragma unroll
    for (int e = 0; e < 4; e++) {
        float2 a = __bfloat1622float2(b2[e]);
        float2 r;
        r.x = s * g_w[j + 2 * e]     * a.x;
        r.y = s * g_w[j + 2 * e + 1] * a.y;
        o2[e] = __float22bfloat162_rn(r);
    }
    *(uint4*)(g_G + base) = outv;
}

// ---------------------------------------------------------------------------
// k_gemm: 128x128 upper-triangle tile (bi<=bj), bf16 mma.sync + ldmatrix.
// K-chunk 64, double-buffered dynamic smem (72 KB), 1 sync per chunk.
// ---------------------------------------------------------------------------
static constexpr int KC  = 64;
static constexpr int LDT = 72;
static constexpr int BUF = 128 * LDT * 2;          // 18432 bytes
static constexpr int SMEM_DYN = 4 * BUF;           // 73728

__global__ void __launch_bounds__(256, 2) k_gemm(int pass, float* out, long long covBase) {
    extern __shared__ __align__(16) char dsm[];

    int rem = blockIdx.x;
    int bi = 0;
    while (rem >= NB - bi) { rem -= NB - bi; bi++; }
    int bj = bi + rem;
    int i0 = bi * 128, j0 = bj * 128;

    const __nv_bfloat16* Aop = g_G;
    const __nv_bfloat16* Bop = (pass == 1) ? g_G : g_H;

    int tid = threadIdx.x, lane = tid & 31, wid = tid >> 5;
    int wr = wid >> 2, wc = wid & 3;
    int gID = lane >> 2, tig = lane & 3;

    uint32_t sAu = smem_u32(dsm);
    uint32_t sBu = sAu + 2 * BUF;

    int la16 = lane & 15, lkh = lane >> 4;
    uint32_t aoff[4];
#pragma unroll
    for (int mi = 0; mi < 4; mi++)
        aoff[mi] = (uint32_t)(((wr * 64 + mi * 16 + la16) * LDT + lkh * 8) * 2);
    uint32_t boff4[2];
#pragma unroll
    for (int p = 0; p < 2; p++) {
        int nrow = wc * 32 + (2 * p + (lane >> 4)) * 8 + (lane & 7);
        int kh = (lane >> 3) & 1;
        boff4[p] = (uint32_t)((nrow * LDT + kh * 8) * 2);
    }

    float acc[4][4][4];
#pragma unroll
    for (int a = 0; a < 4; a++)
#pragma unroll
        for (int b = 0; b < 4; b++)
#pragma unroll
            for (int c = 0; c < 4; c++) acc[a][b][c] = 0.f;

    int r_[4], g_[4];
    uint32_t soff[4];
#pragma unroll
    for (int t = 0; t < 4; t++) {
        int q = tid + t * 256;
        r_[t] = q >> 3; g_[t] = q & 7;
        soff[t] = (uint32_t)(r_[t] * LDT + g_[t] * 8) * 2;
    }

#pragma unroll
    for (int t = 0; t < 4; t++) {
        cp16(sAu + soff[t], Aop + (size_t)(i0 + r_[t]) * N + g_[t] * 8);
        cp16(sBu + soff[t], Bop + (size_t)(j0 + r_[t]) * N + g_[t] * 8);
    }
    CP_COMMIT();
    CP_WAITN(0);
    __syncthreads();

    const int NCH = N / KC;
    for (int c = 0; c < NCH; c++) {
        uint32_t bufo = (uint32_t)(c & 1) * BUF;
        if (c + 1 < NCH) {
            int kc = (c + 1) * KC;
            uint32_t bo = (uint32_t)((c + 1) & 1) * BUF;
#pragma unroll
            for (int t = 0; t < 4; t++) {
                cp16(sAu + bo + soff[t], Aop + (size_t)(i0 + r_[t]) * N + kc + g_[t] * 8);
                cp16(sBu + bo + soff[t], Bop + (size_t)(j0 + r_[t]) * N + kc + g_[t] * 8);
            }
            CP_COMMIT();
        }
#pragma unroll
        for (int kk = 0; kk < KC; kk += 16) {
            uint32_t af[4][4], bfr[2][4];
#pragma unroll
            for (int mi = 0; mi < 4; mi++)
                ldmatrix_x4(af[mi], sAu + bufo + aoff[mi] + kk * 2);
#pragma unroll
            for (int p = 0; p < 2; p++)
                ldmatrix_x4(bfr[p], sBu + bufo + boff4[p] + kk * 2);
#pragma unroll
            for (int mi = 0; mi < 4; mi++)
#pragma unroll
                for (int ni = 0; ni < 4; ni++)
                    mma_bf16(acc[mi][ni], af[mi], &bfr[ni >> 1][(ni & 1) * 2]);
        }
        if (c + 1 < NCH) CP_WAITN(0);
        __syncthreads();
    }

#pragma unroll
    for (int mi = 0; mi < 4; mi++) {
#pragma unroll
        for (int r8 = 0; r8 < 2; r8++) {
            int row = i0 + wr * 64 + mi * 16 + gID + r8 * 8;
            if (pass == 1) {
                __nv_bfloat16* dst = g_H + (size_t)row * N;
                const __nv_bfloat16* gsrc = g_G + (size_t)row * N;
#pragma unroll
                for (int ni = 0; ni < 4; ni++) {
                    int col = j0 + wc * 32 + ni * 8 + tig * 2;
                    float2 v;
                    v.x = acc[mi][ni][r8 * 2 + 0] + __bfloat162float(gsrc[col]);
                    v.y = acc[mi][ni][r8 * 2 + 1] + __bfloat162float(gsrc[col + 1]);
                    *(__nv_bfloat162*)(dst + col) = __float22bfloat162_rn(v);
                }
            } else {
                const float* jsrc = g_Js + (size_t)row * N;
                float mrow = g_m[0][row];
                float inv_wr = 1.0f / g_w[row];
#pragma unroll
                for (int ni = 0; ni < 4; ni++) {
                    int col = j0 + wc * 32 + ni * 8 + tig * 2;
#pragma unroll
                    for (int e = 0; e < 2; e++) {
                        int gj = col + e;
                        if (gj > row) {
                            float S = acc[mi][ni][r8 * 2 + e];
                            float cov = mrow * g_m[0][gj]
                                      + CINV * (CINV * jsrc[gj] * g_d[gj] + S * g_w[gj] * inv_wr);
                            out[covBase + (size_t)row * N + gj] = cov;
                        }
                    }
                }
            }
        }
    }
}

// ---------------------------------------------------------------------------
// k_mirrorH: H[r][c] = H[c][r] for r > c
// ---------------------------------------------------------------------------
__global__ void k_mirrorH() {
    int bx = blockIdx.x, by = blockIdx.y;
    if (by < bx) return;
    __shared__ __nv_bfloat16 t[32][33];
    int tx = threadIdx.x, ty = threadIdx.y;
    t[ty][tx] = g_H[(size_t)(bx * 32 + ty) * N + (by * 32 + tx)];
    __syncthreads();
    int dr = by * 32 + ty, dc = bx * 32 + tx;
    if (dr > dc) g_H[(size_t)dr * N + dc] = t[tx][ty];
}

// ---------------------------------------------------------------------------
// kernel_launch
// ---------------------------------------------------------------------------
extern "C" void kernel_launch(void* const* d_in, const int* in_sizes, int n_in,
                              void* d_out, int out_size) {
    const float* h = nullptr;
    const float* J = nullptr;
    for (int i = 0; i < n_in; i++) {
        if (in_sizes[i] == N * N)   J = (const float*)d_in[i];
        else if (in_sizes[i] == N)  h = (const float*)d_in[i];
    }
    float* out = (float*)d_out;
    long long covBase = ((long long)out_size >= (long long)N * N + N) ? N : 0;

    cudaFuncSetAttribute(k_gemm, cudaFuncAttributeMaxDynamicSharedMemorySize, SMEM_DYN);

    k_zero_tri<<<N, 256>>>(out, covBase);
    k_prep<<<NT * (NT + 1) / 2, dim3(32, 32)>>>(J);
    k_minit<<<16, 256>>>(h);
    for (int t = 0; t < TOT_ITERS; t++) {
        if (t < SPLIT) k_iter_bf16<<<N / 4, 256>>>(h, t & 1);
        else           k_iter_f32 <<<N / 2, 256>>>(h, t & 1);
    }
    k_vec<<<16, 256>>>(out, covBase > 0 ? 1 : 0);
    k_buildG<<<(int)(((size_t)N * N / 8 + 255) / 256), 256>>>();
    k_gemm<<<NB * (NB + 1) / 2, 256, SMEM_DYN>>>(1, out, covBase);
    k_mirrorH<<<dim3(N / 32, N / 32), dim3(32, 32)>>>();
    k_gemm<<<NB * (NB + 1) / 2, 256, SMEM_DYN>>>(2, out, covBase);
}

// round 14
// speedup vs baseline: 1.0353x; 1.0353x over previous
#include <cuda_runtime.h>
#include <cuda_bf16.h>
#include <cstdint>
#include <cstddef>

static constexpr int   N     = 4096;
static constexpr int   NB    = 32;            // 128-tiles per side
static constexpr int   NT    = 128;           // 32-tiles per side
static constexpr int   TOT_ITERS = 12;        // 10 bf16 + 2 fp32 polish (even -> m ends in g_m[0])
static constexpr int   SPLIT = 10;
static constexpr float CINV  = 1.0f / 1.000001f;

// ---------------------------------------------------------------------------
// Device scratch (allocation-free rule: __device__ globals)
// ---------------------------------------------------------------------------
static __device__ float         g_Js[(size_t)N * N];  // 64 MB symmetrized J (fp32)
static __device__ __nv_bfloat16 g_G [(size_t)N * N];  // 32 MB: Js(bf16) during iters, then G
static __device__ __nv_bfloat16 g_H [(size_t)N * N];  // 32 MB: H = G + G^2
static __device__ float         g_m [2][N];
static __device__ float         g_d [N];
static __device__ float         g_w [N];

// ---------------------------------------------------------------------------
// PTX wrappers (baseline PTX only: sm_75/sm_80 features, compute_103-safe)
// ---------------------------------------------------------------------------
__device__ __forceinline__ void mma_bf16(float* c, const uint32_t* a, const uint32_t* b) {
    asm volatile(
        "mma.sync.aligned.m16n8k16.row.col.f32.bf16.bf16.f32 "
        "{%0,%1,%2,%3}, {%4,%5,%6,%7}, {%8,%9}, {%0,%1,%2,%3};\n"
        : "+f"(c[0]), "+f"(c[1]), "+f"(c[2]), "+f"(c[3])
        : "r"(a[0]), "r"(a[1]), "r"(a[2]), "r"(a[3]), "r"(b[0]), "r"(b[1]));
}
__device__ __forceinline__ void ldmatrix_x4(uint32_t* r, uint32_t addr) {
    asm volatile("ldmatrix.sync.aligned.m8n8.x4.shared.b16 {%0,%1,%2,%3}, [%4];"
                 : "=r"(r[0]), "=r"(r[1]), "=r"(r[2]), "=r"(r[3]) : "r"(addr));
}
__device__ __forceinline__ uint32_t smem_u32(const void* p) {
    uint32_t a;
    asm("{ .reg .u64 t; cvta.to.shared.u64 t, %1; cvt.u32.u64 %0, t; }" : "=r"(a) : "l"(p));
    return a;
}
__device__ __forceinline__ void cp16(uint32_t dst, const void* src) {
    asm volatile("cp.async.cg.shared.global [%0], [%1], 16;" :: "r"(dst), "l"(src));
}
#define CP_COMMIT()  asm volatile("cp.async.commit_group;" ::: "memory")
#define CP_WAITN(n)  asm volatile("cp.async.wait_group %0;" :: "n"(n) : "memory")

// ---------------------------------------------------------------------------
// k_zero_tri: zero cov lower triangle + diagonal
// ---------------------------------------------------------------------------
__global__ void k_zero_tri(float* out, long long covBase) {
    int r = blockIdx.x;
    float* row = out + covBase + (size_t)r * N;
    int nz = r + 1;
    int nq = nz >> 2;
    float4* row4 = (float4*)row;
    for (int q = threadIdx.x; q < nq; q += blockDim.x)
        row4[q] = make_float4(0.f, 0.f, 0.f, 0.f);
    int tail = nq << 2;
    if (threadIdx.x < nz - tail) row[tail + threadIdx.x] = 0.f;
}

// ---------------------------------------------------------------------------
// k_prep: Js = sym(J) with zero diag (fp32) + bf16 copy; tile-pair version
// ---------------------------------------------------------------------------
__global__ void k_prep(const float* __restrict__ J) {
    int rem = blockIdx.x;
    int bi = 0;
    while (rem >= NT - bi) { rem -= NT - bi; bi++; }
    int bj = bi + rem;
    __shared__ float ta[32][33];
    __shared__ float tb[32][33];
    int r = threadIdx.y, c = threadIdx.x;
    ta[r][c] = J[(size_t)(bi * 32 + r) * N + (bj * 32 + c)];
    tb[r][c] = J[(size_t)(bj * 32 + r) * N + (bi * 32 + c)];
    __syncthreads();
    {
        int gi = bi * 32 + r, gj = bj * 32 + c;
        float v = (gi == gj) ? 0.0f : 0.5f * (ta[r][c] + tb[c][r]);
        size_t idx = (size_t)gi * N + gj;
        g_Js[idx] = v;
        g_G[idx]  = __float2bfloat16(v);
    }
    if (bi != bj) {
        int gi = bj * 32 + r, gj = bi * 32 + c;
        float v = 0.5f * (tb[r][c] + ta[c][r]);
        size_t idx = (size_t)gi * N + gj;
        g_Js[idx] = v;
        g_G[idx]  = __float2bfloat16(v);
    }
}

// ---------------------------------------------------------------------------
// m0 = tanh(h)
// ---------------------------------------------------------------------------
__global__ void k_minit(const float* __restrict__ h) {
    int i = blockIdx.x * blockDim.x + threadIdx.x;
    if (i < N) g_m[0][i] = tanhf(h[i]);
}

// ---------------------------------------------------------------------------
// bf16 iteration: 4 rows/CTA, 4-stage cp.async pipeline, BARRIER-FREE stages
// (each thread consumes exactly the smem bytes it copied)
// ---------------------------------------------------------------------------
__global__ void __launch_bounds__(256) k_iter_bf16(const float* __restrict__ h, int pin) {
    __shared__ __align__(16) __nv_bfloat16 sj[4][N];   // 32 KB
    int row0 = blockIdx.x * 4;
    const float* mi_v = g_m[pin];
    const float4* mv = (const float4*)mi_v;
    uint32_t sb = smem_u32(&sj[0][0]);
    int tid = threadIdx.x;
    int half = tid >> 7;          // 0 or 1
    int tcol = tid & 127;
    int r0 = half * 2;

#pragma unroll
    for (int s = 0; s < 4; s++) {
#pragma unroll
        for (int p = 0; p < 2; p++) {
            int r = r0 + p;
            int cc = 128 * s + tcol;                       // 16B chunk (8 bf16)
            cp16(sb + ((uint32_t)r * N + (uint32_t)cc * 8) * 2,
                 g_G + (size_t)(row0 + r) * N + (size_t)cc * 8);
        }
        CP_COMMIT();
    }

    float s1[2] = {0.f, 0.f}, s2[2] = {0.f, 0.f};
#pragma unroll
    for (int s = 0; s < 4; s++) {
        if      (s == 0) CP_WAITN(3);
        else if (s == 1) CP_WAITN(2);
        else if (s == 2) CP_WAITN(1);
        else             CP_WAITN(0);
        int cc = 128 * s + tcol;
        float4 ma = mv[2 * cc], mb = mv[2 * cc + 1];
        float pa[8] = {ma.x, ma.y, ma.z, ma.w, mb.x, mb.y, mb.z, mb.w};
        float pb[8];
#pragma unroll
        for (int e = 0; e < 8; e++) pb[e] = pa[e] * (1.f - pa[e]);
#pragma unroll
        for (int p = 0; p < 2; p++) {
            uint4 v = *(const uint4*)&sj[r0 + p][cc * 8];
            const __nv_bfloat162* b2 = reinterpret_cast<const __nv_bfloat162*>(&v);
            float2 a0 = __bfloat1622float2(b2[0]);
            float2 a1 = __bfloat1622float2(b2[1]);
            float2 a2 = __bfloat1622float2(b2[2]);
            float2 a3 = __bfloat1622float2(b2[3]);
            float av[8] = {a0.x, a0.y, a1.x, a1.y, a2.x, a2.y, a3.x, a3.y};
#pragma unroll
            for (int e = 0; e < 8; e++) {
                s1[p] = fmaf(av[e], pa[e], s1[p]);
                s2[p] = fmaf(av[e] * av[e], pb[e], s2[p]);
            }
        }
    }

    __shared__ float rs1[8][2], rs2[8][2];
    int lane = tid & 31, w = tid >> 5;
#pragma unroll
    for (int p = 0; p < 2; p++) {
#pragma unroll
        for (int o = 16; o; o >>= 1) {
            s1[p] += __shfl_xor_sync(0xFFFFFFFFu, s1[p], o);
            s2[p] += __shfl_xor_sync(0xFFFFFFFFu, s2[p], o);
        }
        if (lane == 0) { rs1[w][p] = s1[p]; rs2[w][p] = s2[p]; }
    }
    __syncthreads();
    if (tid < 4) {
        int r = tid;
        int wbase = (r >> 1) * 4;
        int idx = r & 1;
        float a = 0.f, b = 0.f;
#pragma unroll
        for (int ww = 0; ww < 4; ww++) { a += rs1[wbase + ww][idx]; b += rs2[wbase + ww][idx]; }
        int row = row0 + r;
        float mi = mi_v[row];
        g_m[pin ^ 1][row] = 0.5f * (mi + tanhf(h[row] + a - mi * b));
    }
}

// ---------------------------------------------------------------------------
// fp32 polish: 2 rows/CTA, barrier-free 4-stage pipeline; each thread works
// only on the row it loaded. warps 0-3 -> row 0, warps 4-7 -> row 1.
// ---------------------------------------------------------------------------
__global__ void __launch_bounds__(256) k_iter_f32(const float* __restrict__ h, int pin) {
    __shared__ __align__(16) float sj[2][N];            // 32 KB
    int row0 = blockIdx.x * 2;
    const float* mi_v = g_m[pin];
    const float4* mv = (const float4*)mi_v;
    uint32_t sb = smem_u32(&sj[0][0]);
    int tid = threadIdx.x;
    int half = tid >> 7;
    int tcol = tid & 127;

#pragma unroll
    for (int s = 0; s < 4; s++) {
#pragma unroll
        for (int p = 0; p < 2; p++) {
            int cc = 256 * s + tcol + 128 * p;
            cp16(sb + ((uint32_t)half * N + (uint32_t)cc * 4) * 4,
                 g_Js + (size_t)(row0 + half) * N + (size_t)cc * 4);
        }
        CP_COMMIT();
    }

    float s1 = 0.f, s2 = 0.f;
#pragma unroll
    for (int s = 0; s < 4; s++) {
        if      (s == 0) CP_WAITN(3);
        else if (s == 1) CP_WAITN(2);
        else if (s == 2) CP_WAITN(1);
        else             CP_WAITN(0);
#pragma unroll
        for (int p = 0; p < 2; p++) {
            int cc = 256 * s + tcol + 128 * p;
            float4 a = *(const float4*)&sj[half][cc * 4];
            float4 mq = mv[cc];
            float pa[4] = {mq.x, mq.y, mq.z, mq.w};
            float av[4] = {a.x, a.y, a.z, a.w};
#pragma unroll
            for (int e = 0; e < 4; e++) {
                float pb = pa[e] * (1.f - pa[e]);
                s1 = fmaf(av[e], pa[e], s1);
                s2 = fmaf(av[e] * av[e], pb, s2);
            }
        }
    }

    __shared__ float rs1[8], rs2[8];
    int lane = tid & 31, w = tid >> 5;
#pragma unroll
    for (int o = 16; o; o >>= 1) {
        s1 += __shfl_xor_sync(0xFFFFFFFFu, s1, o);
        s2 += __shfl_xor_sync(0xFFFFFFFFu, s2, o);
    }
    if (lane == 0) { rs1[w] = s1; rs2[w] = s2; }
    __syncthreads();
    if (tid < 2) {
        int r = tid;
        float a = 0.f, b = 0.f;
#pragma unroll
        for (int ww = 0; ww < 4; ww++) { a += rs1[r * 4 + ww]; b += rs2[r * 4 + ww]; }
        int row = row0 + r;
        float mi = mi_v[row];
        g_m[pin ^ 1][row] = 0.5f * (mi + tanhf(h[row] + a - mi * b));
    }
}

// ---------------------------------------------------------------------------
// k_vec: finalize m, compute d, w, write m to out
// ---------------------------------------------------------------------------
__global__ void k_vec(float* out, int writeM) {
    int i = blockIdx.x * blockDim.x + threadIdx.x;
    if (i < N) {
        float m = g_m[0][i];
        float d = 1.0f - m * m;
        g_d[i] = d;
        g_w[i] = sqrtf(d);
        if (writeM) out[i] = m;
    }
}

// ---------------------------------------------------------------------------
// k_buildG: G_ij = CINV * w_i * G_ij * w_j (in-place over bf16(Js))
// ---------------------------------------------------------------------------
__global__ void k_buildG() {
    size_t q = (size_t)blockIdx.x * blockDim.x + threadIdx.x;
    size_t nq = (size_t)N * N / 8;
    if (q >= nq) return;
    size_t base = q * 8;
    int i = (int)(base >> 12);
    int j = (int)(base & (N - 1));
    uint4 v = *(const uint4*)(g_G + base);
    const __nv_bfloat162* b2 = reinterpret_cast<const __nv_bfloat162*>(&v);
    float s = CINV * g_w[i];
    uint4 outv;
    __nv_bfloat162* o2 = reinterpret_cast<__nv_bfloat162*>(&outv);
#pragma unroll
    for (int e = 0; e < 4; e++) {
        float2 a = __bfloat1622float2(b2[e]);
        float2 r;
        r.x = s * g_w[j + 2 * e]     * a.x;
        r.y = s * g_w[j + 2 * e + 1] * a.y;
        o2[e] = __float22bfloat162_rn(r);
    }
    *(uint4*)(g_G + base) = outv;
}

// ---------------------------------------------------------------------------
// k_gemm: 128x128 upper-triangle tile (bi<=bj), bf16 mma.sync + ldmatrix.
// K-chunk 64, double-buffered dynamic smem (72 KB), 1 sync per chunk.
//   pass 1: D = G*G^T       -> H = G + D (bf16)
//   pass 2: D = G*H^T (=S)  -> cov epilogue into out (strictly upper)
// ---------------------------------------------------------------------------
static constexpr int KC  = 64;
static constexpr int LDT = 72;
static constexpr int BUF = 128 * LDT * 2;          // 18432 bytes
static constexpr int SMEM_DYN = 4 * BUF;           // 73728

__global__ void __launch_bounds__(256, 2) k_gemm(int pass, float* out, long long covBase) {
    extern __shared__ __align__(16) char dsm[];

    int rem = blockIdx.x;
    int bi = 0;
    while (rem >= NB - bi) { rem -= NB - bi; bi++; }
    int bj = bi + rem;
    int i0 = bi * 128, j0 = bj * 128;

    const __nv_bfloat16* Aop = g_G;
    const __nv_bfloat16* Bop = (pass == 1) ? g_G : g_H;

    int tid = threadIdx.x, lane = tid & 31, wid = tid >> 5;
    int wr = wid >> 2, wc = wid & 3;
    int gID = lane >> 2, tig = lane & 3;

    uint32_t sAu = smem_u32(dsm);
    uint32_t sBu = sAu + 2 * BUF;

    int la16 = lane & 15, lkh = lane >> 4;
    uint32_t aoff[4];
#pragma unroll
    for (int mi = 0; mi < 4; mi++)
        aoff[mi] = (uint32_t)(((wr * 64 + mi * 16 + la16) * LDT + lkh * 8) * 2);
    uint32_t boff4[2];
#pragma unroll
    for (int p = 0; p < 2; p++) {
        int nrow = wc * 32 + (2 * p + (lane >> 4)) * 8 + (lane & 7);
        int kh = (lane >> 3) & 1;
        boff4[p] = (uint32_t)((nrow * LDT + kh * 8) * 2);
    }

    float acc[4][4][4];
#pragma unroll
    for (int a = 0; a < 4; a++)
#pragma unroll
        for (int b = 0; b < 4; b++)
#pragma unroll
            for (int c = 0; c < 4; c++) acc[a][b][c] = 0.f;

    int r_[4], g_[4];
    uint32_t soff[4];
#pragma unroll
    for (int t = 0; t < 4; t++) {
        int q = tid + t * 256;
        r_[t] = q >> 3; g_[t] = q & 7;
        soff[t] = (uint32_t)(r_[t] * LDT + g_[t] * 8) * 2;
    }

#pragma unroll
    for (int t = 0; t < 4; t++) {
        cp16(sAu + soff[t], Aop + (size_t)(i0 + r_[t]) * N + g_[t] * 8);
        cp16(sBu + soff[t], Bop + (size_t)(j0 + r_[t]) * N + g_[t] * 8);
    }
    CP_COMMIT();
    CP_WAITN(0);
    __syncthreads();

    const int NCH = N / KC;
    for (int c = 0; c < NCH; c++) {
        uint32_t bufo = (uint32_t)(c & 1) * BUF;
        if (c + 1 < NCH) {
            int kc = (c + 1) * KC;
            uint32_t bo = (uint32_t)((c + 1) & 1) * BUF;
#pragma unroll
            for (int t = 0; t < 4; t++) {
                cp16(sAu + bo + soff[t], Aop + (size_t)(i0 + r_[t]) * N + kc + g_[t] * 8);
                cp16(sBu + bo + soff[t], Bop + (size_t)(j0 + r_[t]) * N + kc + g_[t] * 8);
            }
            CP_COMMIT();
        }
#pragma unroll
        for (int kk = 0; kk < KC; kk += 16) {
            uint32_t af[4][4], bfr[2][4];
#pragma unroll
            for (int mi = 0; mi < 4; mi++)
                ldmatrix_x4(af[mi], sAu + bufo + aoff[mi] + kk * 2);
#pragma unroll
            for (int p = 0; p < 2; p++)
                ldmatrix_x4(bfr[p], sBu + bufo + boff4[p] + kk * 2);
#pragma unroll
            for (int mi = 0; mi < 4; mi++)
#pragma unroll
                for (int ni = 0; ni < 4; ni++)
                    mma_bf16(acc[mi][ni], af[mi], &bfr[ni >> 1][(ni & 1) * 2]);
        }
        if (c + 1 < NCH) CP_WAITN(0);
        __syncthreads();
    }

#pragma unroll
    for (int mi = 0; mi < 4; mi++) {
#pragma unroll
        for (int r8 = 0; r8 < 2; r8++) {
            int row = i0 + wr * 64 + mi * 16 + gID + r8 * 8;
            if (pass == 1) {
                __nv_bfloat16* dst = g_H + (size_t)row * N;
                const __nv_bfloat16* gsrc = g_G + (size_t)row * N;
#pragma unroll
                for (int ni = 0; ni < 4; ni++) {
                    int col = j0 + wc * 32 + ni * 8 + tig * 2;
                    float2 v;
                    v.x = acc[mi][ni][r8 * 2 + 0] + __bfloat162float(gsrc[col]);
                    v.y = acc[mi][ni][r8 * 2 + 1] + __bfloat162float(gsrc[col + 1]);
                    *(__nv_bfloat162*)(dst + col) = __float22bfloat162_rn(v);
                }
            } else {
                const float* jsrc = g_Js + (size_t)row * N;
                float mrow = g_m[0][row];
                float inv_wr = 1.0f / g_w[row];
#pragma unroll
                for (int ni = 0; ni < 4; ni++) {
                    int col = j0 + wc * 32 + ni * 8 + tig * 2;
#pragma unroll
                    for (int e = 0; e < 2; e++) {
                        int gj = col + e;
                        if (gj > row) {
                            float S = acc[mi][ni][r8 * 2 + e];
                            float cov = mrow * g_m[0][gj]
                                      + CINV * (CINV * jsrc[gj] * g_d[gj] + S * g_w[gj] * inv_wr);
                            out[covBase + (size_t)row * N + gj] = cov;
                        }
                    }
                }
            }
        }
    }
}

// ---------------------------------------------------------------------------
// k_mirrorH: H[r][c] = H[c][r] for r > c
// ---------------------------------------------------------------------------
__global__ void k_mirrorH() {
    int bx = blockIdx.x, by = blockIdx.y;
    if (by < bx) return;
    __shared__ __nv_bfloat16 t[32][33];
    int tx = threadIdx.x, ty = threadIdx.y;
    t[ty][tx] = g_H[(size_t)(bx * 32 + ty) * N + (by * 32 + tx)];
    __syncthreads();
    int dr = by * 32 + ty, dc = bx * 32 + tx;
    if (dr > dc) g_H[(size_t)dr * N + dc] = t[tx][ty];
}

// ---------------------------------------------------------------------------
// kernel_launch
// ---------------------------------------------------------------------------
extern "C" void kernel_launch(void* const* d_in, const int* in_sizes, int n_in,
                              void* d_out, int out_size) {
    const float* h = nullptr;
    const float* J = nullptr;
    for (int i = 0; i < n_in; i++) {
        if (in_sizes[i] == N * N)   J = (const float*)d_in[i];
        else if (in_sizes[i] == N)  h = (const float*)d_in[i];
    }
    float* out = (float*)d_out;
    long long covBase = ((long long)out_size >= (long long)N * N + N) ? N : 0;

    cudaFuncSetAttribute(k_gemm, cudaFuncAttributeMaxDynamicSharedMemorySize, SMEM_DYN);

    k_zero_tri<<<N, 256>>>(out, covBase);
    k_prep<<<NT * (NT + 1) / 2, dim3(32, 32)>>>(J);
    k_minit<<<16, 256>>>(h);
    for (int t = 0; t < TOT_ITERS; t++) {
        if (t < SPLIT) k_iter_bf16<<<N / 4, 256>>>(h, t & 1);
        else           k_iter_f32 <<<N / 2, 256>>>(h, t & 1);
    }
    k_vec<<<16, 256>>>(out, covBase > 0 ? 1 : 0);
    k_buildG<<<(int)(((size_t)N * N / 8 + 255) / 256), 256>>>();
    k_gemm<<<NB * (NB + 1) / 2, 256, SMEM_DYN>>>(1, out, covBase);
    k_mirrorH<<<dim3(N / 32, N / 32), dim3(32, 32)>>>();
    k_gemm<<<NB * (NB + 1) / 2, 256, SMEM_DYN>>>(2, out, covBase);
}

// round 15
// speedup vs baseline: 1.0585x; 1.0225x over previous
#include <cuda_runtime.h>
#include <cuda_bf16.h>
#include <cstdint>
#include <cstddef>

static constexpr int   N     = 4096;
static constexpr int   NB    = 32;            // 128-tiles per side
static constexpr int   NT    = 128;           // 32-tiles per side
static constexpr int   TOT_ITERS = 10;        // 9 bf16 + 1 fp32 polish (even -> m ends in g_m[0])
static constexpr int   SPLIT = 9;
static constexpr float CINV  = 1.0f / 1.000001f;

// ---------------------------------------------------------------------------
// Device scratch (allocation-free rule: __device__ globals)
// ---------------------------------------------------------------------------
static __device__ float         g_Js[(size_t)N * N];  // 64 MB symmetrized J (fp32)
static __device__ __nv_bfloat16 g_G [(size_t)N * N];  // 32 MB: Js(bf16) during iters, then G
static __device__ __nv_bfloat16 g_H [(size_t)N * N];  // 32 MB: H = G + G^2
static __device__ float         g_m [2][N];
static __device__ float         g_d [N];
static __device__ float         g_w [N];

// ---------------------------------------------------------------------------
// PTX wrappers (baseline PTX only: sm_75/sm_80 features, compute_103-safe)
// ---------------------------------------------------------------------------
__device__ __forceinline__ void mma_bf16(float* c, const uint32_t* a, const uint32_t* b) {
    asm volatile(
        "mma.sync.aligned.m16n8k16.row.col.f32.bf16.bf16.f32 "
        "{%0,%1,%2,%3}, {%4,%5,%6,%7}, {%8,%9}, {%0,%1,%2,%3};\n"
        : "+f"(c[0]), "+f"(c[1]), "+f"(c[2]), "+f"(c[3])
        : "r"(a[0]), "r"(a[1]), "r"(a[2]), "r"(a[3]), "r"(b[0]), "r"(b[1]));
}
__device__ __forceinline__ void ldmatrix_x4(uint32_t* r, uint32_t addr) {
    asm volatile("ldmatrix.sync.aligned.m8n8.x4.shared.b16 {%0,%1,%2,%3}, [%4];"
                 : "=r"(r[0]), "=r"(r[1]), "=r"(r[2]), "=r"(r[3]) : "r"(addr));
}
__device__ __forceinline__ uint32_t smem_u32(const void* p) {
    uint32_t a;
    asm("{ .reg .u64 t; cvta.to.shared.u64 t, %1; cvt.u32.u64 %0, t; }" : "=r"(a) : "l"(p));
    return a;
}
__device__ __forceinline__ void cp16(uint32_t dst, const void* src) {
    asm volatile("cp.async.cg.shared.global [%0], [%1], 16;" :: "r"(dst), "l"(src));
}
#define CP_COMMIT()  asm volatile("cp.async.commit_group;" ::: "memory")
#define CP_WAITN(n)  asm volatile("cp.async.wait_group %0;" :: "n"(n) : "memory")

// ---------------------------------------------------------------------------
// k_zero_tri: zero cov lower triangle + diagonal
// ---------------------------------------------------------------------------
__global__ void k_zero_tri(float* out, long long covBase) {
    int r = blockIdx.x;
    float* row = out + covBase + (size_t)r * N;
    int nz = r + 1;
    int nq = nz >> 2;
    float4* row4 = (float4*)row;
    for (int q = threadIdx.x; q < nq; q += blockDim.x)
        row4[q] = make_float4(0.f, 0.f, 0.f, 0.f);
    int tail = nq << 2;
    if (threadIdx.x < nz - tail) row[tail + threadIdx.x] = 0.f;
}

// ---------------------------------------------------------------------------
// k_prep: Js = sym(J) with zero diag (fp32) + bf16 copy; tile-pair version
// ---------------------------------------------------------------------------
__global__ void k_prep(const float* __restrict__ J) {
    int rem = blockIdx.x;
    int bi = 0;
    while (rem >= NT - bi) { rem -= NT - bi; bi++; }
    int bj = bi + rem;
    __shared__ float ta[32][33];
    __shared__ float tb[32][33];
    int r = threadIdx.y, c = threadIdx.x;
    ta[r][c] = J[(size_t)(bi * 32 + r) * N + (bj * 32 + c)];
    tb[r][c] = J[(size_t)(bj * 32 + r) * N + (bi * 32 + c)];
    __syncthreads();
    {
        int gi = bi * 32 + r, gj = bj * 32 + c;
        float v = (gi == gj) ? 0.0f : 0.5f * (ta[r][c] + tb[c][r]);
        size_t idx = (size_t)gi * N + gj;
        g_Js[idx] = v;
        g_G[idx]  = __float2bfloat16(v);
    }
    if (bi != bj) {
        int gi = bj * 32 + r, gj = bi * 32 + c;
        float v = 0.5f * (tb[r][c] + ta[c][r]);
        size_t idx = (size_t)gi * N + gj;
        g_Js[idx] = v;
        g_G[idx]  = __float2bfloat16(v);
    }
}

// ---------------------------------------------------------------------------
// m0 = tanh(h)
// ---------------------------------------------------------------------------
__global__ void k_minit(const float* __restrict__ h) {
    int i = blockIdx.x * blockDim.x + threadIdx.x;
    if (i < N) g_m[0][i] = tanhf(h[i]);
}

// ---------------------------------------------------------------------------
// bf16 iteration: 4 rows/CTA, 4-stage cp.async pipeline, BARRIER-FREE stages
// (each thread consumes exactly the smem bytes it copied)
// ---------------------------------------------------------------------------
__global__ void __launch_bounds__(256) k_iter_bf16(const float* __restrict__ h, int pin) {
    __shared__ __align__(16) __nv_bfloat16 sj[4][N];   // 32 KB
    int row0 = blockIdx.x * 4;
    const float* mi_v = g_m[pin];
    const float4* mv = (const float4*)mi_v;
    uint32_t sb = smem_u32(&sj[0][0]);
    int tid = threadIdx.x;
    int half = tid >> 7;          // 0 or 1
    int tcol = tid & 127;
    int r0 = half * 2;

#pragma unroll
    for (int s = 0; s < 4; s++) {
#pragma unroll
        for (int p = 0; p < 2; p++) {
            int r = r0 + p;
            int cc = 128 * s + tcol;                       // 16B chunk (8 bf16)
            cp16(sb + ((uint32_t)r * N + (uint32_t)cc * 8) * 2,
                 g_G + (size_t)(row0 + r) * N + (size_t)cc * 8);
        }
        CP_COMMIT();
    }

    float s1[2] = {0.f, 0.f}, s2[2] = {0.f, 0.f};
#pragma unroll
    for (int s = 0; s < 4; s++) {
        if      (s == 0) CP_WAITN(3);
        else if (s == 1) CP_WAITN(2);
        else if (s == 2) CP_WAITN(1);
        else             CP_WAITN(0);
        int cc = 128 * s + tcol;
        float4 ma = mv[2 * cc], mb = mv[2 * cc + 1];
        float pa[8] = {ma.x, ma.y, ma.z, ma.w, mb.x, mb.y, mb.z, mb.w};
        float pb[8];
#pragma unroll
        for (int e = 0; e < 8; e++) pb[e] = pa[e] * (1.f - pa[e]);
#pragma unroll
        for (int p = 0; p < 2; p++) {
            uint4 v = *(const uint4*)&sj[r0 + p][cc * 8];
            const __nv_bfloat162* b2 = reinterpret_cast<const __nv_bfloat162*>(&v);
            float2 a0 = __bfloat1622float2(b2[0]);
            float2 a1 = __bfloat1622float2(b2[1]);
            float2 a2 = __bfloat1622float2(b2[2]);
            float2 a3 = __bfloat1622float2(b2[3]);
            float av[8] = {a0.x, a0.y, a1.x, a1.y, a2.x, a2.y, a3.x, a3.y};
#pragma unroll
            for (int e = 0; e < 8; e++) {
                s1[p] = fmaf(av[e], pa[e], s1[p]);
                s2[p] = fmaf(av[e] * av[e], pb[e], s2[p]);
            }
        }
    }

    __shared__ float rs1[8][2], rs2[8][2];
    int lane = tid & 31, w = tid >> 5;
#pragma unroll
    for (int p = 0; p < 2; p++) {
#pragma unroll
        for (int o = 16; o; o >>= 1) {
            s1[p] += __shfl_xor_sync(0xFFFFFFFFu, s1[p], o);
            s2[p] += __shfl_xor_sync(0xFFFFFFFFu, s2[p], o);
        }
        if (lane == 0) { rs1[w][p] = s1[p]; rs2[w][p] = s2[p]; }
    }
    __syncthreads();
    if (tid < 4) {
        int r = tid;
        int wbase = (r >> 1) * 4;
        int idx = r & 1;
        float a = 0.f, b = 0.f;
#pragma unroll
        for (int ww = 0; ww < 4; ww++) { a += rs1[wbase + ww][idx]; b += rs2[wbase + ww][idx]; }
        int row = row0 + r;
        float mi = mi_v[row];
        g_m[pin ^ 1][row] = 0.5f * (mi + tanhf(h[row] + a - mi * b));
    }
}

// ---------------------------------------------------------------------------
// fp32 polish: 2 rows/CTA, barrier-free 4-stage pipeline; each thread works
// only on the row it loaded. warps 0-3 -> row 0, warps 4-7 -> row 1.
// ---------------------------------------------------------------------------
__global__ void __launch_bounds__(256) k_iter_f32(const float* __restrict__ h, int pin) {
    __shared__ __align__(16) float sj[2][N];            // 32 KB
    int row0 = blockIdx.x * 2;
    const float* mi_v = g_m[pin];
    const float4* mv = (const float4*)mi_v;
    uint32_t sb = smem_u32(&sj[0][0]);
    int tid = threadIdx.x;
    int half = tid >> 7;
    int tcol = tid & 127;

#pragma unroll
    for (int s = 0; s < 4; s++) {
#pragma unroll
        for (int p = 0; p < 2; p++) {
            int cc = 256 * s + tcol + 128 * p;
            cp16(sb + ((uint32_t)half * N + (uint32_t)cc * 4) * 4,
                 g_Js + (size_t)(row0 + half) * N + (size_t)cc * 4);
        }
        CP_COMMIT();
    }

    float s1 = 0.f, s2 = 0.f;
#pragma unroll
    for (int s = 0; s < 4; s++) {
        if      (s == 0) CP_WAITN(3);
        else if (s == 1) CP_WAITN(2);
        else if (s == 2) CP_WAITN(1);
        else             CP_WAITN(0);
#pragma unroll
        for (int p = 0; p < 2; p++) {
            int cc = 256 * s + tcol + 128 * p;
            float4 a = *(const float4*)&sj[half][cc * 4];
            float4 mq = mv[cc];
            float pa[4] = {mq.x, mq.y, mq.z, mq.w};
            float av[4] = {a.x, a.y, a.z, a.w};
#pragma unroll
            for (int e = 0; e < 4; e++) {
                float pb = pa[e] * (1.f - pa[e]);
                s1 = fmaf(av[e], pa[e], s1);
                s2 = fmaf(av[e] * av[e], pb, s2);
            }
        }
    }

    __shared__ float rs1[8], rs2[8];
    int lane = tid & 31, w = tid >> 5;
#pragma unroll
    for (int o = 16; o; o >>= 1) {
        s1 += __shfl_xor_sync(0xFFFFFFFFu, s1, o);
        s2 += __shfl_xor_sync(0xFFFFFFFFu, s2, o);
    }
    if (lane == 0) { rs1[w] = s1; rs2[w] = s2; }
    __syncthreads();
    if (tid < 2) {
        int r = tid;
        float a = 0.f, b = 0.f;
#pragma unroll
        for (int ww = 0; ww < 4; ww++) { a += rs1[r * 4 + ww]; b += rs2[r * 4 + ww]; }
        int row = row0 + r;
        float mi = mi_v[row];
        g_m[pin ^ 1][row] = 0.5f * (mi + tanhf(h[row] + a - mi * b));
    }
}

// ---------------------------------------------------------------------------
// k_vec: finalize m, compute d, w, write m to out
// ---------------------------------------------------------------------------
__global__ void k_vec(float* out, int writeM) {
    int i = blockIdx.x * blockDim.x + threadIdx.x;
    if (i < N) {
        float m = g_m[0][i];
        float d = 1.0f - m * m;
        g_d[i] = d;
        g_w[i] = sqrtf(d);
        if (writeM) out[i] = m;
    }
}

// ---------------------------------------------------------------------------
// k_buildG: G_ij = CINV * w_i * G_ij * w_j (in-place over bf16(Js))
// ---------------------------------------------------------------------------
__global__ void k_buildG() {
    size_t q = (size_t)blockIdx.x * blockDim.x + threadIdx.x;
    size_t nq = (size_t)N * N / 8;
    if (q >= nq) return;
    size_t base = q * 8;
    int i = (int)(base >> 12);
    int j = (int)(base & (N - 1));
    uint4 v = *(const uint4*)(g_G + base);
    const __nv_bfloat162* b2 = reinterpret_cast<const __nv_bfloat162*>(&v);
    float s = CINV * g_w[i];
    uint4 outv;
    __nv_bfloat162* o2 = reinterpret_cast<__nv_bfloat162*>(&outv);
#pragma unroll
    for (int e = 0; e < 4; e++) {
        float2 a = __bfloat1622float2(b2[e]);
        float2 r;
        r.x = s * g_w[j + 2 * e]     * a.x;
        r.y = s * g_w[j + 2 * e + 1] * a.y;
        o2[e] = __float22bfloat162_rn(r);
    }
    *(uint4*)(g_G + base) = outv;
}

// ---------------------------------------------------------------------------
// k_gemm: 128x128 upper-triangle tile (bi<=bj), bf16 mma.sync + ldmatrix.
// K-chunk 64, double-buffered dynamic smem (72 KB), 1 sync per chunk.
//   pass 1: D = G*G^T       -> H = G + D (bf16)
//   pass 2: D = G*H^T (=S)  -> cov epilogue into out (strictly upper)
// ---------------------------------------------------------------------------
static constexpr int KC  = 64;
static constexpr int LDT = 72;
static constexpr int BUF = 128 * LDT * 2;          // 18432 bytes
static constexpr int SMEM_DYN = 4 * BUF;           // 73728

__global__ void __launch_bounds__(256, 2) k_gemm(int pass, float* out, long long covBase) {
    extern __shared__ __align__(16) char dsm[];

    int rem = blockIdx.x;
    int bi = 0;
    while (rem >= NB - bi) { rem -= NB - bi; bi++; }
    int bj = bi + rem;
    int i0 = bi * 128, j0 = bj * 128;

    const __nv_bfloat16* Aop = g_G;
    const __nv_bfloat16* Bop = (pass == 1) ? g_G : g_H;

    int tid = threadIdx.x, lane = tid & 31, wid = tid >> 5;
    int wr = wid >> 2, wc = wid & 3;
    int gID = lane >> 2, tig = lane & 3;

    uint32_t sAu = smem_u32(dsm);
    uint32_t sBu = sAu + 2 * BUF;

    int la16 = lane & 15, lkh = lane >> 4;
    uint32_t aoff[4];
#pragma unroll
    for (int mi = 0; mi < 4; mi++)
        aoff[mi] = (uint32_t)(((wr * 64 + mi * 16 + la16) * LDT + lkh * 8) * 2);
    uint32_t boff4[2];
#pragma unroll
    for (int p = 0; p < 2; p++) {
        int nrow = wc * 32 + (2 * p + (lane >> 4)) * 8 + (lane & 7);
        int kh = (lane >> 3) & 1;
        boff4[p] = (uint32_t)((nrow * LDT + kh * 8) * 2);
    }

    float acc[4][4][4];
#pragma unroll
    for (int a = 0; a < 4; a++)
#pragma unroll
        for (int b = 0; b < 4; b++)
#pragma unroll
            for (int c = 0; c < 4; c++) acc[a][b][c] = 0.f;

    int r_[4], g_[4];
    uint32_t soff[4];
#pragma unroll
    for (int t = 0; t < 4; t++) {
        int q = tid + t * 256;
        r_[t] = q >> 3; g_[t] = q & 7;
        soff[t] = (uint32_t)(r_[t] * LDT + g_[t] * 8) * 2;
    }

#pragma unroll
    for (int t = 0; t < 4; t++) {
        cp16(sAu + soff[t], Aop + (size_t)(i0 + r_[t]) * N + g_[t] * 8);
        cp16(sBu + soff[t], Bop + (size_t)(j0 + r_[t]) * N + g_[t] * 8);
    }
    CP_COMMIT();
    CP_WAITN(0);
    __syncthreads();

    const int NCH = N / KC;
    for (int c = 0; c < NCH; c++) {
        uint32_t bufo = (uint32_t)(c & 1) * BUF;
        if (c + 1 < NCH) {
            int kc = (c + 1) * KC;
            uint32_t bo = (uint32_t)((c + 1) & 1) * BUF;
#pragma unroll
            for (int t = 0; t < 4; t++) {
                cp16(sAu + bo + soff[t], Aop + (size_t)(i0 + r_[t]) * N + kc + g_[t] * 8);
                cp16(sBu + bo + soff[t], Bop + (size_t)(j0 + r_[t]) * N + kc + g_[t] * 8);
            }
            CP_COMMIT();
        }
#pragma unroll
        for (int kk = 0; kk < KC; kk += 16) {
            uint32_t af[4][4], bfr[2][4];
#pragma unroll
            for (int mi = 0; mi < 4; mi++)
                ldmatrix_x4(af[mi], sAu + bufo + aoff[mi] + kk * 2);
#pragma unroll
            for (int p = 0; p < 2; p++)
                ldmatrix_x4(bfr[p], sBu + bufo + boff4[p] + kk * 2);
#pragma unroll
            for (int mi = 0; mi < 4; mi++)
#pragma unroll
                for (int ni = 0; ni < 4; ni++)
                    mma_bf16(acc[mi][ni], af[mi], &bfr[ni >> 1][(ni & 1) * 2]);
        }
        if (c + 1 < NCH) {
            CP_WAITN(0);
            __syncthreads();
        }
    }

#pragma unroll
    for (int mi = 0; mi < 4; mi++) {
#pragma unroll
        for (int r8 = 0; r8 < 2; r8++) {
            int row = i0 + wr * 64 + mi * 16 + gID + r8 * 8;
            if (pass == 1) {
                __nv_bfloat16* dst = g_H + (size_t)row * N;
                const __nv_bfloat16* gsrc = g_G + (size_t)row * N;
#pragma unroll
                for (int ni = 0; ni < 4; ni++) {
                    int col = j0 + wc * 32 + ni * 8 + tig * 2;
                    float2 v;
                    v.x = acc[mi][ni][r8 * 2 + 0] + __bfloat162float(gsrc[col]);
                    v.y = acc[mi][ni][r8 * 2 + 1] + __bfloat162float(gsrc[col + 1]);
                    *(__nv_bfloat162*)(dst + col) = __float22bfloat162_rn(v);
                }
            } else {
                const float* jsrc = g_Js + (size_t)row * N;
                float mrow = g_m[0][row];
                float inv_wr = 1.0f / g_w[row];
#pragma unroll
                for (int ni = 0; ni < 4; ni++) {
                    int col = j0 + wc * 32 + ni * 8 + tig * 2;
#pragma unroll
                    for (int e = 0; e < 2; e++) {
                        int gj = col + e;
                        if (gj > row) {
                            float S = acc[mi][ni][r8 * 2 + e];
                            float cov = mrow * g_m[0][gj]
                                      + CINV * (CINV * jsrc[gj] * g_d[gj] + S * g_w[gj] * inv_wr);
                            out[covBase + (size_t)row * N + gj] = cov;
                        }
                    }
                }
            }
        }
    }
}

// ---------------------------------------------------------------------------
// k_mirrorH: H[r][c] = H[c][r] for r > c
// ---------------------------------------------------------------------------
__global__ void k_mirrorH() {
    int bx = blockIdx.x, by = blockIdx.y;
    if (by < bx) return;
    __shared__ __nv_bfloat16 t[32][33];
    int tx = threadIdx.x, ty = threadIdx.y;
    t[ty][tx] = g_H[(size_t)(bx * 32 + ty) * N + (by * 32 + tx)];
    __syncthreads();
    int dr = by * 32 + ty, dc = bx * 32 + tx;
    if (dr > dc) g_H[(size_t)dr * N + dc] = t[tx][ty];
}

// ---------------------------------------------------------------------------
// kernel_launch
// ---------------------------------------------------------------------------
extern "C" void kernel_launch(void* const* d_in, const int* in_sizes, int n_in,
                              void* d_out, int out_size) {
    const float* h = nullptr;
    const float* J = nullptr;
    for (int i = 0; i < n_in; i++) {
        if (in_sizes[i] == N * N)   J = (const float*)d_in[i];
        else if (in_sizes[i] == N)  h = (const float*)d_in[i];
    }
    float* out = (float*)d_out;
    long long covBase = ((long long)out_size >= (long long)N * N + N) ? N : 0;

    cudaFuncSetAttribute(k_gemm, cudaFuncAttributeMaxDynamicSharedMemorySize, SMEM_DYN);

    k_zero_tri<<<N, 256>>>(out, covBase);
    k_prep<<<NT * (NT + 1) / 2, dim3(32, 32)>>>(J);
    k_minit<<<16, 256>>>(h);
    for (int t = 0; t < TOT_ITERS; t++) {
        if (t < SPLIT) k_iter_bf16<<<N / 4, 256>>>(h, t & 1);
        else           k_iter_f32 <<<N / 2, 256>>>(h, t & 1);
    }
    k_vec<<<16, 256>>>(out, covBase > 0 ? 1 : 0);
    k_buildG<<<(int)(((size_t)N * N / 8 + 255) / 256), 256>>>();
    k_gemm<<<NB * (NB + 1) / 2, 256, SMEM_DYN>>>(1, out, covBase);
    k_mirrorH<<<dim3(N / 32, N / 32), dim3(32, 32)>>>();
    k_gemm<<<NB * (NB + 1) / 2, 256, SMEM_DYN>>>(2, out, covBase);
}

// round 16
// speedup vs baseline: 1.0773x; 1.0178x over previous
#include <cuda_runtime.h>
#include <cuda_bf16.h>
#include <cstdint>
#include <cstddef>

static constexpr int   N     = 4096;
static constexpr int   NB    = 32;            // 128-tiles per side
static constexpr int   NT    = 128;           // 32-tiles per side
static constexpr int   TOT_ITERS = 9;         // 9 bf16, no fp32 polish (odd -> m ends in g_m[1])
static constexpr float CINV  = 1.0f / 1.000001f;

// ---------------------------------------------------------------------------
// Device scratch (allocation-free rule: __device__ globals)
// ---------------------------------------------------------------------------
static __device__ float         g_Js[(size_t)N * N];  // 64 MB symmetrized J (fp32)
static __device__ __nv_bfloat16 g_G [(size_t)N * N];  // 32 MB: Js(bf16) during iters, then G
static __device__ __nv_bfloat16 g_H [(size_t)N * N];  // 32 MB: H = G + G^2
static __device__ float         g_m [2][N];
static __device__ float         g_d [N];
static __device__ float         g_w [N];

// ---------------------------------------------------------------------------
// PTX wrappers (baseline PTX only: sm_75/sm_80 features, compute_103-safe)
// ---------------------------------------------------------------------------
__device__ __forceinline__ void mma_bf16(float* c, const uint32_t* a, const uint32_t* b) {
    asm volatile(
        "mma.sync.aligned.m16n8k16.row.col.f32.bf16.bf16.f32 "
        "{%0,%1,%2,%3}, {%4,%5,%6,%7}, {%8,%9}, {%0,%1,%2,%3};\n"
        : "+f"(c[0]), "+f"(c[1]), "+f"(c[2]), "+f"(c[3])
        : "r"(a[0]), "r"(a[1]), "r"(a[2]), "r"(a[3]), "r"(b[0]), "r"(b[1]));
}
__device__ __forceinline__ void ldmatrix_x4(uint32_t* r, uint32_t addr) {
    asm volatile("ldmatrix.sync.aligned.m8n8.x4.shared.b16 {%0,%1,%2,%3}, [%4];"
                 : "=r"(r[0]), "=r"(r[1]), "=r"(r[2]), "=r"(r[3]) : "r"(addr));
}
__device__ __forceinline__ uint32_t smem_u32(const void* p) {
    uint32_t a;
    asm("{ .reg .u64 t; cvta.to.shared.u64 t, %1; cvt.u32.u64 %0, t; }" : "=r"(a) : "l"(p));
    return a;
}
__device__ __forceinline__ void cp16(uint32_t dst, const void* src) {
    asm volatile("cp.async.cg.shared.global [%0], [%1], 16;" :: "r"(dst), "l"(src));
}
#define CP_COMMIT()  asm volatile("cp.async.commit_group;" ::: "memory")
#define CP_WAITN(n)  asm volatile("cp.async.wait_group %0;" :: "n"(n) : "memory")

// ---------------------------------------------------------------------------
// k_zero_tri: zero cov lower triangle + diagonal
// ---------------------------------------------------------------------------
__global__ void k_zero_tri(float* out, long long covBase) {
    int r = blockIdx.x;
    float* row = out + covBase + (size_t)r * N;
    int nz = r + 1;
    int nq = nz >> 2;
    float4* row4 = (float4*)row;
    for (int q = threadIdx.x; q < nq; q += blockDim.x)
        row4[q] = make_float4(0.f, 0.f, 0.f, 0.f);
    int tail = nq << 2;
    if (threadIdx.x < nz - tail) row[tail + threadIdx.x] = 0.f;
}

// ---------------------------------------------------------------------------
// k_prep: Js = sym(J) with zero diag (fp32) + bf16 copy; tile-pair version
// ---------------------------------------------------------------------------
__global__ void k_prep(const float* __restrict__ J) {
    int rem = blockIdx.x;
    int bi = 0;
    while (rem >= NT - bi) { rem -= NT - bi; bi++; }
    int bj = bi + rem;
    __shared__ float ta[32][33];
    __shared__ float tb[32][33];
    int r = threadIdx.y, c = threadIdx.x;
    ta[r][c] = J[(size_t)(bi * 32 + r) * N + (bj * 32 + c)];
    tb[r][c] = J[(size_t)(bj * 32 + r) * N + (bi * 32 + c)];
    __syncthreads();
    {
        int gi = bi * 32 + r, gj = bj * 32 + c;
        float v = (gi == gj) ? 0.0f : 0.5f * (ta[r][c] + tb[c][r]);
        size_t idx = (size_t)gi * N + gj;
        g_Js[idx] = v;
        g_G[idx]  = __float2bfloat16(v);
    }
    if (bi != bj) {
        int gi = bj * 32 + r, gj = bi * 32 + c;
        float v = 0.5f * (tb[r][c] + ta[c][r]);
        size_t idx = (size_t)gi * N + gj;
        g_Js[idx] = v;
        g_G[idx]  = __float2bfloat16(v);
    }
}

// ---------------------------------------------------------------------------
// m0 = tanh(h)
// ---------------------------------------------------------------------------
__global__ void k_minit(const float* __restrict__ h) {
    int i = blockIdx.x * blockDim.x + threadIdx.x;
    if (i < N) g_m[0][i] = tanhf(h[i]);
}

// ---------------------------------------------------------------------------
// bf16 iteration: 4 rows/CTA, 4-stage cp.async pipeline, BARRIER-FREE stages
// (each thread consumes exactly the smem bytes it copied)
// ---------------------------------------------------------------------------
__global__ void __launch_bounds__(256) k_iter_bf16(const float* __restrict__ h, int pin) {
    __shared__ __align__(16) __nv_bfloat16 sj[4][N];   // 32 KB
    int row0 = blockIdx.x * 4;
    const float* mi_v = g_m[pin];
    const float4* mv = (const float4*)mi_v;
    uint32_t sb = smem_u32(&sj[0][0]);
    int tid = threadIdx.x;
    int half = tid >> 7;          // 0 or 1
    int tcol = tid & 127;
    int r0 = half * 2;

#pragma unroll
    for (int s = 0; s < 4; s++) {
#pragma unroll
        for (int p = 0; p < 2; p++) {
            int r = r0 + p;
            int cc = 128 * s + tcol;                       // 16B chunk (8 bf16)
            cp16(sb + ((uint32_t)r * N + (uint32_t)cc * 8) * 2,
                 g_G + (size_t)(row0 + r) * N + (size_t)cc * 8);
        }
        CP_COMMIT();
    }

    float s1[2] = {0.f, 0.f}, s2[2] = {0.f, 0.f};
#pragma unroll
    for (int s = 0; s < 4; s++) {
        if      (s == 0) CP_WAITN(3);
        else if (s == 1) CP_WAITN(2);
        else if (s == 2) CP_WAITN(1);
        else             CP_WAITN(0);
        int cc = 128 * s + tcol;
        float4 ma = mv[2 * cc], mb = mv[2 * cc + 1];
        float pa[8] = {ma.x, ma.y, ma.z, ma.w, mb.x, mb.y, mb.z, mb.w};
        float pb[8];
#pragma unroll
        for (int e = 0; e < 8; e++) pb[e] = pa[e] * (1.f - pa[e]);
#pragma unroll
        for (int p = 0; p < 2; p++) {
            uint4 v = *(const uint4*)&sj[r0 + p][cc * 8];
            const __nv_bfloat162* b2 = reinterpret_cast<const __nv_bfloat162*>(&v);
            float2 a0 = __bfloat1622float2(b2[0]);
            float2 a1 = __bfloat1622float2(b2[1]);
            float2 a2 = __bfloat1622float2(b2[2]);
            float2 a3 = __bfloat1622float2(b2[3]);
            float av[8] = {a0.x, a0.y, a1.x, a1.y, a2.x, a2.y, a3.x, a3.y};
#pragma unroll
            for (int e = 0; e < 8; e++) {
                s1[p] = fmaf(av[e], pa[e], s1[p]);
                s2[p] = fmaf(av[e] * av[e], pb[e], s2[p]);
            }
        }
    }

    __shared__ float rs1[8][2], rs2[8][2];
    int lane = tid & 31, w = tid >> 5;
#pragma unroll
    for (int p = 0; p < 2; p++) {
#pragma unroll
        for (int o = 16; o; o >>= 1) {
            s1[p] += __shfl_xor_sync(0xFFFFFFFFu, s1[p], o);
            s2[p] += __shfl_xor_sync(0xFFFFFFFFu, s2[p], o);
        }
        if (lane == 0) { rs1[w][p] = s1[p]; rs2[w][p] = s2[p]; }
    }
    __syncthreads();
    if (tid < 4) {
        int r = tid;
        int wbase = (r >> 1) * 4;
        int idx = r & 1;
        float a = 0.f, b = 0.f;
#pragma unroll
        for (int ww = 0; ww < 4; ww++) { a += rs1[wbase + ww][idx]; b += rs2[wbase + ww][idx]; }
        int row = row0 + r;
        float mi = mi_v[row];
        g_m[pin ^ 1][row] = 0.5f * (mi + tanhf(h[row] + a - mi * b));
    }
}

// ---------------------------------------------------------------------------
// k_vec: finalize m (read from g_m[src]), canonicalize into g_m[0],
// compute d, w, write m to out
// ---------------------------------------------------------------------------
__global__ void k_vec(float* out, int writeM, int src) {
    int i = blockIdx.x * blockDim.x + threadIdx.x;
    if (i < N) {
        float m = g_m[src][i];
        float d = 1.0f - m * m;
        g_m[0][i] = m;
        g_d[i] = d;
        g_w[i] = sqrtf(d);
        if (writeM) out[i] = m;
    }
}

// ---------------------------------------------------------------------------
// k_buildG: G_ij = CINV * w_i * G_ij * w_j (in-place over bf16(Js))
// ---------------------------------------------------------------------------
__global__ void k_buildG() {
    size_t q = (size_t)blockIdx.x * blockDim.x + threadIdx.x;
    size_t nq = (size_t)N * N / 8;
    if (q >= nq) return;
    size_t base = q * 8;
    int i = (int)(base >> 12);
    int j = (int)(base & (N - 1));
    uint4 v = *(const uint4*)(g_G + base);
    const __nv_bfloat162* b2 = reinterpret_cast<const __nv_bfloat162*>(&v);
    float s = CINV * g_w[i];
    uint4 outv;
    __nv_bfloat162* o2 = reinterpret_cast<__nv_bfloat162*>(&outv);
#pragma unroll
    for (int e = 0; e < 4; e++) {
        float2 a = __bfloat1622float2(b2[e]);
        float2 r;
        r.x = s * g_w[j + 2 * e]     * a.x;
        r.y = s * g_w[j + 2 * e + 1] * a.y;
        o2[e] = __float22bfloat162_rn(r);
    }
    *(uint4*)(g_G + base) = outv;
}

// ---------------------------------------------------------------------------
// k_gemm: 128x128 upper-triangle tile (bi<=bj), bf16 mma.sync + ldmatrix.
// K-chunk 64, double-buffered dynamic smem (72 KB), 1 sync per chunk.
//   pass 1: D = G*G^T       -> H = G + D (bf16)
//   pass 2: D = G*H^T (=S)  -> cov epilogue into out (strictly upper)
// ---------------------------------------------------------------------------
static constexpr int KC  = 64;
static constexpr int LDT = 72;
static constexpr int BUF = 128 * LDT * 2;          // 18432 bytes
static constexpr int SMEM_DYN = 4 * BUF;           // 73728

__global__ void __launch_bounds__(256, 2) k_gemm(int pass, float* out, long long covBase) {
    extern __shared__ __align__(16) char dsm[];

    int rem = blockIdx.x;
    int bi = 0;
    while (rem >= NB - bi) { rem -= NB - bi; bi++; }
    int bj = bi + rem;
    int i0 = bi * 128, j0 = bj * 128;

    const __nv_bfloat16* Aop = g_G;
    const __nv_bfloat16* Bop = (pass == 1) ? g_G : g_H;

    int tid = threadIdx.x, lane = tid & 31, wid = tid >> 5;
    int wr = wid >> 2, wc = wid & 3;
    int gID = lane >> 2, tig = lane & 3;

    uint32_t sAu = smem_u32(dsm);
    uint32_t sBu = sAu + 2 * BUF;

    int la16 = lane & 15, lkh = lane >> 4;
    uint32_t aoff[4];
#pragma unroll
    for (int mi = 0; mi < 4; mi++)
        aoff[mi] = (uint32_t)(((wr * 64 + mi * 16 + la16) * LDT + lkh * 8) * 2);
    uint32_t boff4[2];
#pragma unroll
    for (int p = 0; p < 2; p++) {
        int nrow = wc * 32 + (2 * p + (lane >> 4)) * 8 + (lane & 7);
        int kh = (lane >> 3) & 1;
        boff4[p] = (uint32_t)((nrow * LDT + kh * 8) * 2);
    }

    float acc[4][4][4];
#pragma unroll
    for (int a = 0; a < 4; a++)
#pragma unroll
        for (int b = 0; b < 4; b++)
#pragma unroll
            for (int c = 0; c < 4; c++) acc[a][b][c] = 0.f;

    int r_[4], g_[4];
    uint32_t soff[4];
#pragma unroll
    for (int t = 0; t < 4; t++) {
        int q = tid + t * 256;
        r_[t] = q >> 3; g_[t] = q & 7;
        soff[t] = (uint32_t)(r_[t] * LDT + g_[t] * 8) * 2;
    }

#pragma unroll
    for (int t = 0; t < 4; t++) {
        cp16(sAu + soff[t], Aop + (size_t)(i0 + r_[t]) * N + g_[t] * 8);
        cp16(sBu + soff[t], Bop + (size_t)(j0 + r_[t]) * N + g_[t] * 8);
    }
    CP_COMMIT();
    CP_WAITN(0);
    __syncthreads();

    const int NCH = N / KC;
    for (int c = 0; c < NCH; c++) {
        uint32_t bufo = (uint32_t)(c & 1) * BUF;
        if (c + 1 < NCH) {
            int kc = (c + 1) * KC;
            uint32_t bo = (uint32_t)((c + 1) & 1) * BUF;
#pragma unroll
            for (int t = 0; t < 4; t++) {
                cp16(sAu + bo + soff[t], Aop + (size_t)(i0 + r_[t]) * N + kc + g_[t] * 8);
                cp16(sBu + bo + soff[t], Bop + (size_t)(j0 + r_[t]) * N + kc + g_[t] * 8);
            }
            CP_COMMIT();
        }
#pragma unroll
        for (int kk = 0; kk < KC; kk += 16) {
            uint32_t af[4][4], bfr[2][4];
#pragma unroll
            for (int mi = 0; mi < 4; mi++)
                ldmatrix_x4(af[mi], sAu + bufo + aoff[mi] + kk * 2);
#pragma unroll
            for (int p = 0; p < 2; p++)
                ldmatrix_x4(bfr[p], sBu + bufo + boff4[p] + kk * 2);
#pragma unroll
            for (int mi = 0; mi < 4; mi++)
#pragma unroll
                for (int ni = 0; ni < 4; ni++)
                    mma_bf16(acc[mi][ni], af[mi], &bfr[ni >> 1][(ni & 1) * 2]);
        }
        if (c + 1 < NCH) {
            CP_WAITN(0);
            __syncthreads();
        }
    }

#pragma unroll
    for (int mi = 0; mi < 4; mi++) {
#pragma unroll
        for (int r8 = 0; r8 < 2; r8++) {
            int row = i0 + wr * 64 + mi * 16 + gID + r8 * 8;
            if (pass == 1) {
                __nv_bfloat16* dst = g_H + (size_t)row * N;
                const __nv_bfloat16* gsrc = g_G + (size_t)row * N;
#pragma unroll
                for (int ni = 0; ni < 4; ni++) {
                    int col = j0 + wc * 32 + ni * 8 + tig * 2;
                    float2 v;
                    v.x = acc[mi][ni][r8 * 2 + 0] + __bfloat162float(gsrc[col]);
                    v.y = acc[mi][ni][r8 * 2 + 1] + __bfloat162float(gsrc[col + 1]);
                    *(__nv_bfloat162*)(dst + col) = __float22bfloat162_rn(v);
                }
            } else {
                const float* jsrc = g_Js + (size_t)row * N;
                float mrow = g_m[0][row];
                float inv_wr = 1.0f / g_w[row];
#pragma unroll
                for (int ni = 0; ni < 4; ni++) {
                    int col = j0 + wc * 32 + ni * 8 + tig * 2;
#pragma unroll
                    for (int e = 0; e < 2; e++) {
                        int gj = col + e;
                        if (gj > row) {
                            float S = acc[mi][ni][r8 * 2 + e];
                            float cov = mrow * g_m[0][gj]
                                      + CINV * (CINV * jsrc[gj] * g_d[gj] + S * g_w[gj] * inv_wr);
                            out[covBase + (size_t)row * N + gj] = cov;
                        }
                    }
                }
            }
        }
    }
}

// ---------------------------------------------------------------------------
// k_mirrorH: H[r][c] = H[c][r] for r > c
// ---------------------------------------------------------------------------
__global__ void k_mirrorH() {
    int bx = blockIdx.x, by = blockIdx.y;
    if (by < bx) return;
    __shared__ __nv_bfloat16 t[32][33];
    int tx = threadIdx.x, ty = threadIdx.y;
    t[ty][tx] = g_H[(size_t)(bx * 32 + ty) * N + (by * 32 + tx)];
    __syncthreads();
    int dr = by * 32 + ty, dc = bx * 32 + tx;
    if (dr > dc) g_H[(size_t)dr * N + dc] = t[tx][ty];
}

// ---------------------------------------------------------------------------
// kernel_launch
// ---------------------------------------------------------------------------
extern "C" void kernel_launch(void* const* d_in, const int* in_sizes, int n_in,
                              void* d_out, int out_size) {
    const float* h = nullptr;
    const float* J = nullptr;
    for (int i = 0; i < n_in; i++) {
        if (in_sizes[i] == N * N)   J = (const float*)d_in[i];
        else if (in_sizes[i] == N)  h = (const float*)d_in[i];
    }
    float* out = (float*)d_out;
    long long covBase = ((long long)out_size >= (long long)N * N + N) ? N : 0;

    cudaFuncSetAttribute(k_gemm, cudaFuncAttributeMaxDynamicSharedMemorySize, SMEM_DYN);

    k_zero_tri<<<N, 256>>>(out, covBase);
    k_prep<<<NT * (NT + 1) / 2, dim3(32, 32)>>>(J);
    k_minit<<<16, 256>>>(h);
    for (int t = 0; t < TOT_ITERS; t++)
        k_iter_bf16<<<N / 4, 256>>>(h, t & 1);
    k_vec<<<16, 256>>>(out, covBase > 0 ? 1 : 0, TOT_ITERS & 1);
    k_buildG<<<(int)(((size_t)N * N / 8 + 255) / 256), 256>>>();
    k_gemm<<<NB * (NB + 1) / 2, 256, SMEM_DYN>>>(1, out, covBase);
    k_mirrorH<<<dim3(N / 32, N / 32), dim3(32, 32)>>>();
    k_gemm<<<NB * (NB + 1) / 2, 256, SMEM_DYN>>>(2, out, covBase);
}